// round 17
// baseline (speedup 1.0000x reference)
#include <cuda_runtime.h>
#include <cstdint>

// ---------------------------------------------------------------------------
// PureCartesianTensorProductO3 — mma.sync TF32, R17.
// M=256 rows/CTA (8 warps x 32 rows = 2 m-tiles each -> W fragments reused 2x),
// interleaved float4 fragment layout: [row][k8][tig] = (hi_k, lo_k, hi_k4, lo_k4),
// row stride 20 float4 (conflict-free LDS.128 / STS.64).
// K=2048 (both ss of s_out-pair), N=32 Z, 3-term TF32 split, atomicAdd epilogue.
// ---------------------------------------------------------------------------

#define NROWS 8192
#define FEAT  832
#define SBLK  416
#define NTH   256

__host__ __device__ constexpr int kP3[3]   = {1, 3, 9};
__host__ __device__ constexpr int kLOFF[3] = {0, 32, 128};
__host__ __device__ constexpr int kL1[15] = {0,0,0,1,1,1,1,1,1,2,2,2,2,2,2};
__host__ __device__ constexpr int kL2[15] = {0,1,2,0,1,1,1,2,2,0,1,1,2,2,2};
__host__ __device__ constexpr int kLO[15] = {0,1,2,1,2,0,1,1,2,2,1,2,2,0,1};
__host__ __device__ constexpr int kUE[15] = {0,0,0,0,0,0,1,0,1,0,0,1,0,0,1};
// rows-per-tile n_sub = floor(256/Mout)
__host__ __device__ constexpr int kNS[15] = {256,85,28,85,28,256,85,85,28,28,85,28,28,256,85};
// CTA offsets: per path 2*ceil(8192/n_sub)  (Mout1:64, Mout3:194, Mout9:586)
__host__ __device__ constexpr int kOFF[16] =
    {0,64,258,844,1038,1624,1688,1882,2076,2662,3248,3442,4028,4614,4678,4872};
#define GRID_TOTAL 4872

// smem float4 layout: slot = row*20 + k8*4 + tig; B rows 256, W rows 32
#define RS   80                  // row stride in floats
#define SB_F 0                   // B: 256*80 = 20480 floats
#define SW_F 20480               // W: 32*80  = 2560 floats
#define SMEM_FLOATS 23040
#define SMEM_BYTES  (SMEM_FLOATS * 4)   // 92160

__device__ __forceinline__ uint32_t f2tf32(float x) {
    uint32_t r; asm("cvt.rna.tf32.f32 %0, %1;" : "=r"(r) : "f"(x)); return r;
}
__device__ __forceinline__ void mma8(float* c, uint32_t a0, uint32_t a1, uint32_t a2,
                                     uint32_t a3, uint32_t b0, uint32_t b1) {
    asm volatile(
        "mma.sync.aligned.m16n8k8.row.col.f32.tf32.tf32.f32 "
        "{%0,%1,%2,%3}, {%4,%5,%6,%7}, {%8,%9}, {%0,%1,%2,%3};"
        : "+f"(c[0]), "+f"(c[1]), "+f"(c[2]), "+f"(c[3])
        : "r"(a0), "r"(a1), "r"(a2), "r"(a3), "r"(b0), "r"(b1));
}

__device__ __forceinline__ float dot3(const float* u, const float* v) {
    return fmaf(u[0], v[0], fmaf(u[1], v[1], u[2] * v[2]));
}
__device__ __forceinline__ void cross3(const float* u, const float* v, float* o) {
    o[0] = u[1] * v[2] - u[2] * v[1];
    o[1] = u[2] * v[0] - u[0] * v[2];
    o[2] = u[0] * v[1] - u[1] * v[0];
}

// Spatial contraction per path (verified against _path_eq; unchanged since R1 fix)
template <int P>
__device__ __forceinline__ void compute_B(const float* t1, const float* t2, float* B) {
    if constexpr (P == 0) {
        B[0] = t1[0] * t2[0];
    } else if constexpr (P == 1) {
        #pragma unroll
        for (int m = 0; m < 3; ++m) B[m] = t1[0] * t2[m];
    } else if constexpr (P == 2) {
        #pragma unroll
        for (int m = 0; m < 9; ++m) B[m] = t1[0] * t2[m];
    } else if constexpr (P == 3) {
        #pragma unroll
        for (int m = 0; m < 3; ++m) B[m] = t1[m] * t2[0];
    } else if constexpr (P == 4) {
        #pragma unroll
        for (int i = 0; i < 3; ++i)
            #pragma unroll
            for (int j = 0; j < 3; ++j) B[3 * i + j] = t1[i] * t2[j];
    } else if constexpr (P == 5) {
        B[0] = dot3(t1, t2);
    } else if constexpr (P == 6) {
        cross3(t1, t2, B);
    } else if constexpr (P == 7) {
        #pragma unroll
        for (int d = 0; d < 3; ++d) B[d] = dot3(t1, t2 + 3 * d);
    } else if constexpr (P == 8) {
        #pragma unroll
        for (int d = 0; d < 3; ++d) cross3(t1, t2 + 3 * d, B + 3 * d);
    } else if constexpr (P == 9) {
        #pragma unroll
        for (int m = 0; m < 9; ++m) B[m] = t1[m] * t2[0];
    } else if constexpr (P == 10) {
        #pragma unroll
        for (int c = 0; c < 3; ++c) B[c] = dot3(t1 + 3 * c, t2);
    } else if constexpr (P == 11) {
        #pragma unroll
        for (int c = 0; c < 3; ++c) cross3(t1 + 3 * c, t2, B + 3 * c);
    } else if constexpr (P == 12) {
        #pragma unroll
        for (int c = 0; c < 3; ++c)
            #pragma unroll
            for (int e = 0; e < 3; ++e) B[3 * c + e] = dot3(t1 + 3 * c, t2 + 3 * e);
    } else if constexpr (P == 13) {
        float s = 0.f;
        #pragma unroll
        for (int i = 0; i < 9; ++i) s = fmaf(t1[i], t2[i], s);
        B[0] = s;
    } else {  // P==14
        float M01 = dot3(t1 + 0, t2 + 3), M02 = dot3(t1 + 0, t2 + 6);
        float M10 = dot3(t1 + 3, t2 + 0), M12 = dot3(t1 + 3, t2 + 6);
        float M20 = dot3(t1 + 6, t2 + 0), M21 = dot3(t1 + 6, t2 + 3);
        B[0] = M12 - M21;
        B[1] = M20 - M02;
        B[2] = M01 - M10;
    }
}

// interleaved hi/lo store: float offset = row*80 + kpart (+0/+2 within pair)
__device__ __forceinline__ void split_store2(float* s, int fo, float x) {
    uint32_t hi = f2tf32(x);
    float lo = x - __uint_as_float(hi);
    float2 v = make_float2(__uint_as_float(hi), __uint_as_float(f2tf32(lo)));
    *reinterpret_cast<float2*>(s + fo) = v;
}

template <int P>
__device__ __noinline__ void proc_path(int rem,
                                       const float* __restrict__ x1,
                                       const float* __restrict__ x2,
                                       const float* __restrict__ wgt,
                                       float* __restrict__ out,
                                       float* smem) {
    constexpr int L1 = kL1[P], L2 = kL2[P], Lo = kLO[P], UE = kUE[P];
    constexpr int d1 = kP3[L1], d2 = kP3[L2], Mout = kP3[Lo];
    constexpr int O1 = kLOFF[L1], O2 = kLOFF[L2], Oo = kLOFF[Lo];
    constexpr int NSUB = kNS[P];
    constexpr int USED = NSUB * Mout;     // 252/255/256

    float* sB = smem + SB_F;
    float* sW = smem + SW_F;
    const float4* sB4 = reinterpret_cast<const float4*>(sB);
    const float4* sW4 = reinterpret_cast<const float4*>(sW);

    const int tid  = threadIdx.x;
    const int w    = tid >> 5;            // warp 0..7 -> rows w*32..w*32+31
    const int lane = tid & 31;
    const int grp  = lane >> 2;           // 0..7
    const int tig  = lane & 3;            // 0..3
    const int pair = rem & 1;
    const int tile = rem >> 1;
    const int n0   = tile * NSUB;
    const int s_out = (pair == 0) ? UE : (1 ^ UE);

    // per-thread staging k decomposition: k -> kpart float offset
    // kpart = (k>>3)*16 + (k&3)*4 + ((k>>2)&1)*2
    const int kS = lane;                  // staging k = lane
    const int kpart = ((kS >> 3) << 4) + ((kS & 3) << 2) + (((kS >> 2) & 1) << 1);

    // zero pad rows once
    if constexpr (USED < 256) {
        for (int t = tid; t < (256 - USED) * 20; t += NTH) {
            int row = USED + t / 20, q = t % 20;
            reinterpret_cast<float4*>(sB)[row * 20 + q] = make_float4(0.f, 0.f, 0.f, 0.f);
        }
    }

    float acc[2][4][4];
    #pragma unroll
    for (int mt = 0; mt < 2; ++mt)
        #pragma unroll
        for (int zt = 0; zt < 4; ++zt)
            #pragma unroll
            for (int i = 0; i < 4; ++i) acc[mt][zt][i] = 0.f;

    #pragma unroll 1
    for (int c = 0; c < 64; ++c) {
        const int ss = (pair == 0) ? ((c >= 32) ? 3 : 0) : ((c >= 32) ? 2 : 1);
        const int s1 = ss >> 1, s2 = ss & 1;
        const int a0 = c & 31;

        __syncthreads();   // prior MMA phase done reading smem (covers pad too)

        // ---- stage W: 32 Z x 32 k  (4 per thread; k = lane)
        {
            const float* wb = wgt + ((size_t)(P * 4 + ss) << 15) + a0 * 32 + kS;
            #pragma unroll
            for (int it = 0; it < 4; ++it) {
                int z = (tid + it * NTH) >> 5;
                float wv = __ldg(wb + (size_t)z * 1024);
                split_store2(sW, z * RS + kpart, wv);
            }
        }
        // ---- stage B: NSUB ln x 32 k (k = lane), Mout rows each
        {
            const float* x1b = x1 + s1 * SBLK + O1 + a0 * d1;
            const float* x2b = x2 + s2 * SBLK + O2 + kS * d2;
            constexpr int TOT = NSUB * 32;
            #pragma unroll 1
            for (int t = tid; t < TOT; t += NTH) {
                int ln = t >> 5;
                int n = n0 + ln; if (n >= NROWS) n = NROWS - 1;
                float t1v[d1], t2v[d2], Bm[Mout];
                const float* p1 = x1b + (size_t)n * FEAT;
                const float* p2 = x2b + (size_t)n * FEAT;
                #pragma unroll
                for (int i = 0; i < d1; ++i) t1v[i] = __ldg(p1 + i);
                #pragma unroll
                for (int j = 0; j < d2; ++j) t2v[j] = __ldg(p2 + j);
                compute_B<P>(t1v, t2v, Bm);
                #pragma unroll
                for (int m = 0; m < Mout; ++m)
                    split_store2(sB, (ln * Mout + m) * RS + kpart, Bm[m]);
            }
        }
        __syncthreads();

        // ---- MMA phase: 4 k8 x (2 m-tiles x 4 Z-tiles x 3 split terms)
        #pragma unroll
        for (int k8 = 0; k8 < 4; ++k8) {
            const int ks = k8 * 4 + tig;
            // W fragments: one float4 per zt
            float4 wq[4];
            #pragma unroll
            for (int zt = 0; zt < 4; ++zt)
                wq[zt] = sW4[(zt * 8 + grp) * 20 + ks];
            // A fragments: 2 m-tiles x 2 row-halves
            #pragma unroll
            for (int mt = 0; mt < 2; ++mt) {
                const int r0 = w * 32 + mt * 16 + grp;
                float4 aq0 = sB4[r0 * 20 + ks];
                float4 aq1 = sB4[(r0 + 8) * 20 + ks];
                uint32_t ah0 = __float_as_uint(aq0.x), al0 = __float_as_uint(aq0.y);
                uint32_t ah2 = __float_as_uint(aq0.z), al2 = __float_as_uint(aq0.w);
                uint32_t ah1 = __float_as_uint(aq1.x), al1 = __float_as_uint(aq1.y);
                uint32_t ah3 = __float_as_uint(aq1.z), al3 = __float_as_uint(aq1.w);
                #pragma unroll
                for (int zt = 0; zt < 4; ++zt) {
                    uint32_t bh0 = __float_as_uint(wq[zt].x), bl0 = __float_as_uint(wq[zt].y);
                    uint32_t bh1 = __float_as_uint(wq[zt].z), bl1 = __float_as_uint(wq[zt].w);
                    mma8(acc[mt][zt], ah0, ah1, ah2, ah3, bh0, bh1);
                    mma8(acc[mt][zt], ah0, ah1, ah2, ah3, bl0, bl1);
                    mma8(acc[mt][zt], al0, al1, al2, al3, bh0, bh1);
                }
            }
        }
    }

    // ---- epilogue: scatter-accumulate
    const int ob = s_out * SBLK + Oo;
    #pragma unroll
    for (int mt = 0; mt < 2; ++mt) {
        #pragma unroll
        for (int h = 0; h < 2; ++h) {
            const int row = w * 32 + mt * 16 + grp + h * 8;
            bool ok = true;
            if constexpr (USED < 256) ok = (row < USED);
            int ln = row / Mout, m = row - ln * Mout;
            int n = n0 + ln;
            if (ok && n < NROWS) {
                float* op = out + (size_t)n * FEAT + ob + m;
                #pragma unroll
                for (int zt = 0; zt < 4; ++zt) {
                    const int z = zt * 8 + 2 * tig;
                    atomicAdd(op + (size_t)z * Mout, acc[mt][zt][h * 2 + 0]);
                    atomicAdd(op + (size_t)(z + 1) * Mout, acc[mt][zt][h * 2 + 1]);
                }
            }
        }
    }
}

__global__ __launch_bounds__(NTH, 2)
void tp_mma_kernel(const float* __restrict__ x1, const float* __restrict__ x2,
                   const float* __restrict__ wgt, float* __restrict__ out) {
    extern __shared__ float smem[];
    const int bid = blockIdx.x;
    if      (bid < kOFF[1])  proc_path<0>(bid - kOFF[0], x1, x2, wgt, out, smem);
    else if (bid < kOFF[2])  proc_path<1>(bid - kOFF[1], x1, x2, wgt, out, smem);
    else if (bid < kOFF[3])  proc_path<2>(bid - kOFF[2], x1, x2, wgt, out, smem);
    else if (bid < kOFF[4])  proc_path<3>(bid - kOFF[3], x1, x2, wgt, out, smem);
    else if (bid < kOFF[5])  proc_path<4>(bid - kOFF[4], x1, x2, wgt, out, smem);
    else if (bid < kOFF[6])  proc_path<5>(bid - kOFF[5], x1, x2, wgt, out, smem);
    else if (bid < kOFF[7])  proc_path<6>(bid - kOFF[6], x1, x2, wgt, out, smem);
    else if (bid < kOFF[8])  proc_path<7>(bid - kOFF[7], x1, x2, wgt, out, smem);
    else if (bid < kOFF[9])  proc_path<8>(bid - kOFF[8], x1, x2, wgt, out, smem);
    else if (bid < kOFF[10]) proc_path<9>(bid - kOFF[9], x1, x2, wgt, out, smem);
    else if (bid < kOFF[11]) proc_path<10>(bid - kOFF[10], x1, x2, wgt, out, smem);
    else if (bid < kOFF[12]) proc_path<11>(bid - kOFF[11], x1, x2, wgt, out, smem);
    else if (bid < kOFF[13]) proc_path<12>(bid - kOFF[12], x1, x2, wgt, out, smem);
    else if (bid < kOFF[14]) proc_path<13>(bid - kOFF[13], x1, x2, wgt, out, smem);
    else                     proc_path<14>(bid - kOFF[14], x1, x2, wgt, out, smem);
}

extern "C" void kernel_launch(void* const* d_in, const int* in_sizes, int n_in,
                              void* d_out, int out_size) {
    const float* x1  = (const float*)d_in[0];
    const float* x2  = (const float*)d_in[1];
    const float* wgt = (const float*)d_in[2];
    float* out = (float*)d_out;

    cudaFuncSetAttribute(tp_mma_kernel, cudaFuncAttributeMaxDynamicSharedMemorySize, SMEM_BYTES);
    cudaMemsetAsync(d_out, 0, (size_t)out_size * sizeof(float), 0);
    tp_mma_kernel<<<GRID_TOTAL, NTH, SMEM_BYTES>>>(x1, x2, wgt, out);
}